// round 14
// baseline (speedup 1.0000x reference)
#include <cuda_runtime.h>

#define B_ 32
#define S_ 4
#define L_ 64
#define C_ 32
#define H_ 4
#define D_ 8
#define CP_ 16

typedef unsigned long long u64;

__device__ __forceinline__ u64 fma2(u64 a, u64 b, u64 c){
    u64 d; asm("fma.rn.f32x2 %0,%1,%2,%3;" : "=l"(d) : "l"(a),"l"(b),"l"(c)); return d;
}
__device__ __forceinline__ u64 mul2(u64 a, u64 b){
    u64 d; asm("mul.rn.f32x2 %0,%1,%2;" : "=l"(d) : "l"(a),"l"(b)); return d;
}
__device__ __forceinline__ u64 add2(u64 a, u64 b){
    u64 d; asm("add.rn.f32x2 %0,%1,%2;" : "=l"(d) : "l"(a),"l"(b)); return d;
}
__device__ __forceinline__ u64 pack2(float lo, float hi){
    u64 d; asm("mov.b64 %0,{%1,%2};" : "=l"(d) : "f"(lo),"f"(hi)); return d;
}
__device__ __forceinline__ float2 unpack2(u64 v){
    float x,y; asm("mov.b64 {%0,%1},%2;" : "=f"(x),"=f"(y) : "l"(v)); return make_float2(x,y);
}

__device__ float g_xbuf[B_*S_*L_*C_];

__device__ __forceinline__ int keyf(int r){
    return ((((r>>2)&7) ^ (((r>>5)&1)<<2)) << 2);
}
__device__ __forceinline__ int xi(int r, int c){ return r*36 + (c ^ keyf(r)); }

// ---------------------------------------------------------------------------
// Kernel A: one block per (b,s), 1024 threads. (frozen R13)
// ---------------------------------------------------------------------------
#define QSOFF 2304
#define KSOFF 4608
#define VSOFF 6912
#define GWOFF 13568
#define GBOFF 13824
#define WQ2U 6928
#define WK2U 7472
#define WV2U 8016
#define WO2U 8560
#define KA_SMEM (18208*4)
#define BKI(l,m) (9216 + (l)*68 + (m))

__global__ void __launch_bounds__(1024) kA(
    const float* __restrict__ chip0, const float* __restrict__ chip1,
    const float* __restrict__ chip2, const float* __restrict__ chip3,
    const float* __restrict__ bulk,
    const float* __restrict__ we_w, const float* __restrict__ we_b,
    const float* __restrict__ pos,
    const float* __restrict__ mn_g, const float* __restrict__ mn_b,
    const float* __restrict__ wq, const float* __restrict__ bq,
    const float* __restrict__ wk, const float* __restrict__ bk,
    const float* __restrict__ wv, const float* __restrict__ bv,
    const float* __restrict__ wo, const float* __restrict__ bo,
    const float* __restrict__ an_g, const float* __restrict__ an_b,
    const float* __restrict__ conv_w, const float* __restrict__ conv_b,
    const float* __restrict__ gate_w, const float* __restrict__ gate_b)
{
    extern __shared__ float sm[];
    u64* smu = reinterpret_cast<u64*>(sm);
    const int t = threadIdx.x;
    const int b = blockIdx.x >> 2, s = blockIdx.x & 3;
    const float* chip = (s==0)?chip0:(s==1)?chip1:(s==2)?chip2:chip3;

    for (int idx = t; idx < 512; idx += 1024) {
        const int r = idx >> 4, c2 = idx & 15;
        const int o = r*17 + c2;
        float2 a;
        a = *reinterpret_cast<const float2*>(&wq[idx*2]); smu[WQ2U + o] = *reinterpret_cast<u64*>(&a);
        a = *reinterpret_cast<const float2*>(&wk[idx*2]); smu[WK2U + o] = *reinterpret_cast<u64*>(&a);
        a = *reinterpret_cast<const float2*>(&wv[idx*2]); smu[WV2U + o] = *reinterpret_cast<u64*>(&a);
        a = *reinterpret_cast<const float2*>(&wo[idx*2]); smu[WO2U + o] = *reinterpret_cast<u64*>(&a);
    }
    for (int idx = t; idx < L_*L_; idx += 1024)
        sm[BKI(idx>>6, idx&63)] = bulk[b*L_*L_ + idx];
    if (t < 256) sm[GWOFF + t] = gate_w[t];
    if (t >= 256 && t < 288) sm[GBOFF + t - 256] = gate_b[t - 256];

    // phase 1
    {
        const int l = t >> 4, q = t & 15, c0 = q*2;
        const float sig = chip[b*L_ + l];
        const float2 ww = *reinterpret_cast<const float2*>(&we_w[c0]);
        const float2 wb = *reinterpret_cast<const float2*>(&we_b[c0]);
        const float2 pp = *reinterpret_cast<const float2*>(&pos[l*C_ + c0]);
        const float v0 = fmaf(sig, ww.x, wb.x) + pp.x;
        const float v1 = fmaf(sig, ww.y, wb.y) + pp.y;
        float s1 = v0 + v1, s2 = v0*v0 + v1*v1;
        #pragma unroll
        for (int o = 1; o < 16; o <<= 1) {
            s1 += __shfl_xor_sync(0xffffffffu, s1, o);
            s2 += __shfl_xor_sync(0xffffffffu, s2, o);
        }
        const float mean = s1*(1.f/C_);
        const float rstd = rsqrtf(s2*(1.f/C_) - mean*mean + 1e-5f);
        sm[xi(l,c0)]   = (v0-mean)*rstd*mn_g[c0]   + mn_b[c0];
        sm[xi(l,c0+1)] = (v1-mean)*rstd*mn_g[c0+1] + mn_b[c0+1];
    }
    __syncthreads();

    // phase 2
    {
        const int co = t & 31, lbase = (t >> 5) * 2;
        const int x0b = lbase*18,     k0h = keyf(lbase)   >> 1;
        const int x1b = (lbase+1)*18, k1h = keyf(lbase+1) >> 1;
        const int wrow = co*17;
        u64 aq0=0, aq1=0, ak0=0, ak1=0, av0=0, av1=0;
        #pragma unroll 8
        for (int c2 = 0; c2 < 16; c2++) {
            const u64 x0 = smu[x0b + (c2 ^ k0h)];
            const u64 x1 = smu[x1b + (c2 ^ k1h)];
            const u64 wqv = smu[WQ2U + wrow + c2];
            const u64 wkv = smu[WK2U + wrow + c2];
            const u64 wvv = smu[WV2U + wrow + c2];
            aq0 = fma2(x0, wqv, aq0); aq1 = fma2(x1, wqv, aq1);
            ak0 = fma2(x0, wkv, ak0); ak1 = fma2(x1, wkv, ak1);
            av0 = fma2(x0, wvv, av0); av1 = fma2(x1, wvv, av1);
        }
        const float ibq = bq[co], ibk = bk[co], ibv = bv[co];
        float2 f;
        f = unpack2(aq0); sm[QSOFF + xi(lbase,co)]   = f.x + f.y + ibq;
        f = unpack2(aq1); sm[QSOFF + xi(lbase+1,co)] = f.x + f.y + ibq;
        f = unpack2(ak0); sm[KSOFF + xi(lbase,co)]   = f.x + f.y + ibk;
        f = unpack2(ak1); sm[KSOFF + xi(lbase+1,co)] = f.x + f.y + ibk;
        f = unpack2(av0); sm[VSOFF + xi(lbase,co)]   = f.x + f.y + ibv;
        f = unpack2(av1); sm[VSOFF + xi(lbase+1,co)] = f.x + f.y + ibv;
    }
    __syncthreads();

    // phase 3
    {
        const int h = t >> 8, rem = t & 255;
        const int l = rem >> 2, quarter = rem & 3;
        const int hc = h*D_;
        const float rsd = 0.35355339059327373f;

        ulonglong2 qa = *reinterpret_cast<const ulonglong2*>(&sm[QSOFF + xi(l,hc)]);
        ulonglong2 qb = *reinterpret_cast<const ulonglong2*>(&sm[QSOFF + xi(l,hc+4)]);
        const u64 rsd2 = pack2(rsd, rsd);
        qa.x = mul2(qa.x, rsd2); qa.y = mul2(qa.y, rsd2);
        qb.x = mul2(qb.x, rsd2); qb.y = mul2(qb.y, rsd2);
        const float cw = conv_w[h], cb = conv_b[h];

        float Z = 0.f;
        u64 A0 = 0ull, A1 = 0ull, A2 = 0ull, A3 = 0ull;

        #pragma unroll 4
        for (int mm = 0; mm < 16; mm++) {
            const int m = mm*4 + quarter;
            const ulonglong2 ka = *reinterpret_cast<const ulonglong2*>(&sm[KSOFF + xi(m,hc)]);
            const ulonglong2 kb = *reinterpret_cast<const ulonglong2*>(&sm[KSOFF + xi(m,hc+4)]);
            u64 u = mul2(qa.x, ka.x);
            u = fma2(qa.y, ka.y, u);
            u = fma2(qb.x, kb.x, u);
            u = fma2(qb.y, kb.y, u);
            const float2 uf = unpack2(u);
            const float sc = uf.x + uf.y + fmaf(sm[BKI(l,m)], cw, cb);
            const float p = __expf(sc);
            Z += p;
            const u64 pp = pack2(p, p);
            const ulonglong2 va = *reinterpret_cast<const ulonglong2*>(&sm[VSOFF + xi(m,hc)]);
            const ulonglong2 vb = *reinterpret_cast<const ulonglong2*>(&sm[VSOFF + xi(m,hc+4)]);
            A0 = fma2(pp, va.x, A0); A1 = fma2(pp, va.y, A1);
            A2 = fma2(pp, vb.x, A2); A3 = fma2(pp, vb.y, A3);
        }
        #pragma unroll
        for (int o = 1; o < 4; o <<= 1) {
            Z  += __shfl_xor_sync(0xffffffffu, Z, o);
            A0 = add2(A0, __shfl_xor_sync(0xffffffffu, A0, o));
            A1 = add2(A1, __shfl_xor_sync(0xffffffffu, A1, o));
            A2 = add2(A2, __shfl_xor_sync(0xffffffffu, A2, o));
            A3 = add2(A3, __shfl_xor_sync(0xffffffffu, A3, o));
        }

        const float inv = 1.f/Z;
        const float2 f0 = unpack2(A0), f1 = unpack2(A1), f2 = unpack2(A2), f3 = unpack2(A3);
        float o[D_];
        o[0]=f0.x*inv; o[1]=f0.y*inv; o[2]=f1.x*inv; o[3]=f1.y*inv;
        o[4]=f2.x*inv; o[5]=f2.y*inv; o[6]=f3.x*inv; o[7]=f3.y*inv;
        const int d0 = quarter*2;
        float2 og;
        #pragma unroll
        for (int k = 0; k < 2; k++) {
            const int d = d0 + k;
            const float4 w0 = *reinterpret_cast<const float4*>(&sm[GWOFF + h*64 + d*8]);
            const float4 w1 = *reinterpret_cast<const float4*>(&sm[GWOFF + h*64 + d*8 + 4]);
            float g = sm[GBOFF + hc + d];
            g += w0.x*o[0] + w0.y*o[1] + w0.z*o[2] + w0.w*o[3];
            g += w1.x*o[4] + w1.y*o[5] + w1.z*o[6] + w1.w*o[7];
            (&og.x)[k] = __fdividef(o[d], 1.f + __expf(-g));
        }
        __syncthreads();
        *reinterpret_cast<float2*>(&sm[QSOFF + xi(l, hc + d0)]) = og;
    }
    __syncthreads();

    // phase 4
    {
        const int co = t & 31, lbase = (t >> 5) * 2;
        const int x0b = lbase*18,     k0h = keyf(lbase)   >> 1;
        const int x1b = (lbase+1)*18, k1h = keyf(lbase+1) >> 1;
        const int wrow = co*17;
        u64 a0 = 0, a1 = 0;
        #pragma unroll 8
        for (int c2 = 0; c2 < 16; c2++) {
            const u64 w = smu[WO2U + wrow + c2];
            a0 = fma2(smu[(QSOFF>>1) + x0b + (c2 ^ k0h)], w, a0);
            a1 = fma2(smu[(QSOFF>>1) + x1b + (c2 ^ k1h)], w, a1);
        }
        const float ib = bo[co];
        const float2 fa = unpack2(a0), fb = unpack2(a1);
        const float v0 = sm[xi(lbase,co)]   + fa.x + fa.y + ib;
        const float v1 = sm[xi(lbase+1,co)] + fb.x + fb.y + ib;

        u64 S1 = pack2(v0, v1), S2 = pack2(v0*v0, v1*v1);
        #pragma unroll
        for (int o = 1; o < 32; o <<= 1) {
            S1 = add2(S1, __shfl_xor_sync(0xffffffffu, S1, o));
            S2 = add2(S2, __shfl_xor_sync(0xffffffffu, S2, o));
        }
        const float2 s1 = unpack2(S1), s2 = unpack2(S2);
        const float m0 = s1.x*(1.f/C_), m1 = s1.y*(1.f/C_);
        const float r0 = rsqrtf(s2.x*(1.f/C_) - m0*m0 + 1e-5f);
        const float r1 = rsqrtf(s2.y*(1.f/C_) - m1*m1 + 1e-5f);
        const float ag = an_g[co], ab = an_b[co];
        float* dst = g_xbuf + ((b*S_ + s)*L_ + lbase)*C_ + co;
        dst[0]   = (v0 - m0)*r0*ag + ab;
        dst[C_]  = (v1 - m1)*r1*ag + ab;
    }
}

// ---------------------------------------------------------------------------
// Kernel kWB v5: grid = (b, i-group-of-8) = 256 blocks, 512 threads, 2/SM.
// Phase 4: warp = p, 8 i's (4 u64 accs), pp_w column in regs, WIT p-XOR key.
// Phase 5: single pass, warp = (ii, jhalf); full unroll keeps XOR perm static.
// smem floats: MT@0 (32c x 68j), WIT@2176 (8ii x 32d x 20p), RNV@7296 (64).
// Total 7360 floats = 29440 B -> 2 blocks/SM.
// ---------------------------------------------------------------------------
#define MT   0
#define WIT  2176
#define RNV  7296
#define KWB_SMEM (7360*4)

__global__ void __launch_bounds__(512, 2) kWB(
    const float* __restrict__ pp_w, const float* __restrict__ pp_b,
    const float* __restrict__ ada_g, const float* __restrict__ ada_b,
    const float* __restrict__ ada_alpha, float* __restrict__ out)
{
    extern __shared__ float smw[];
    const int t = threadIdx.x;
    const int b = blockIdx.x >> 3, i0 = (blockIdx.x & 7) * 8;
    const float* xb = g_xbuf + b*S_*L_*C_;

    // phase 1: max over tracks -> mT[c][j]
    for (int idx = t; idx < L_*C_; idx += 512) {
        const int j = idx >> 5, c = idx & 31;
        const float m = fmaxf(fmaxf(xb[idx], xb[2048+idx]),
                              fmaxf(xb[4096+idx], xb[6144+idx]));
        smw[MT + c*68 + j] = m;
    }
    __syncthreads();

    // phase 2: rinv per j
    if (t < L_) {
        float ss = 0.f;
        #pragma unroll
        for (int c = 0; c < C_; c++) { const float v = smw[MT + c*68 + t]; ss += v*v; }
        smw[RNV + t] = rsqrtf(ss);
    }
    __syncthreads();

    // phase 3: normalize mT
    for (int idx = t; idx < L_*C_; idx += 512) {
        const int j = idx & 63, c = idx >> 6;
        smw[MT + c*68 + j] *= smw[RNV + j];
    }
    __syncthreads();

    // phase 4: wi. warp = p (16 warps), lane = d; 8 i's -> 4 u64 accs.
    {
        const int p = t >> 5, d = t & 31;
        const int pk = p ^ (((d >> 3) & 3) << 2);
        float wreg[32];
        #pragma unroll
        for (int c = 0; c < 32; c++) wreg[c] = pp_w[p*1024 + c*32 + d];
        u64 acc[4];
        #pragma unroll
        for (int k = 0; k < 4; k++) acc[k] = 0ull;
        #pragma unroll 4
        for (int c = 0; c < 32; c++) {
            const float* mb = &smw[MT + c*68 + i0];
            const ulonglong2 ma = *reinterpret_cast<const ulonglong2*>(mb);    // broadcast
            const ulonglong2 mc = *reinterpret_cast<const ulonglong2*>(mb+4);
            const u64 w2 = pack2(wreg[c], wreg[c]);
            acc[0] = fma2(ma.x, w2, acc[0]); acc[1] = fma2(ma.y, w2, acc[1]);
            acc[2] = fma2(mc.x, w2, acc[2]); acc[3] = fma2(mc.y, w2, acc[3]);
        }
        #pragma unroll
        for (int k = 0; k < 4; k++) {
            const float2 f = unpack2(acc[k]);
            smw[WIT + (2*k)*640   + d*20 + pk] = f.x;
            smw[WIT + (2*k+1)*640 + d*20 + pk] = f.y;
        }
    }
    __syncthreads();

    // phase 5: pair gemm + AdaNorm + SiLU. warp = (ii, jhalf); lane = j.
    // Single pass; full unroll keeps the p-XOR chunk permutation static.
    {
        const int w = t >> 5, lane = t & 31;
        const int jj = (w & 1)*32 + lane;
        const int ii = w >> 1;
        const int i = i0 + ii;
        const float alpha = ada_alpha[0];

        u64 acc[8];
        #pragma unroll
        for (int k = 0; k < 8; k++) acc[k] = 0ull;

        #pragma unroll
        for (int c = 0; c < 32; c++) {
            const int kk = (c >> 3) & 3;                 // compile-time
            const float mj = smw[MT + c*68 + jj];        // conflict-free
            const u64 m2 = pack2(mj, mj);
            const float* wb = &smw[WIT + ii*640 + c*20];
            ulonglong2 wv[4];
            wv[0] = *reinterpret_cast<const ulonglong2*>(wb);       // broadcast
            wv[1] = *reinterpret_cast<const ulonglong2*>(wb+4);
            wv[2] = *reinterpret_cast<const ulonglong2*>(wb+8);
            wv[3] = *reinterpret_cast<const ulonglong2*>(wb+12);
            #pragma unroll
            for (int u = 0; u < 4; u++) {
                const int g = u ^ kk;
                acc[2*g]   = fma2(wv[u].x, m2, acc[2*g]);
                acc[2*g+1] = fma2(wv[u].y, m2, acc[2*g+1]);
            }
        }

        float feat[16];
        float s1 = 0.f, s2 = 0.f;
        #pragma unroll
        for (int k = 0; k < 8; k++) {
            const float2 f = unpack2(acc[k]);
            const float v0 = f.x + pp_b[2*k];
            const float v1 = f.y + pp_b[2*k+1];
            feat[2*k] = v0; feat[2*k+1] = v1;
            s1 += v0 + v1; s2 += v0*v0 + v1*v1;
        }
        const float mu = s1*(1.f/CP_);
        const float rstd = rsqrtf(s2*(1.f/CP_) - mu*mu + 1e-5f);

        #pragma unroll
        for (int p = 0; p < CP_; p++) {
            const float v = feat[p];
            const float ln = (v - mu)*rstd*ada_g[p] + ada_b[p];
            const float val = v + alpha*ln;
            out[((b*CP_ + p)*L_ + i)*L_ + jj] =
                __fdividef(val, 1.f + __expf(-val));
        }
    }
}

extern "C" void kernel_launch(void* const* d_in, const int* in_sizes, int n_in,
                              void* d_out, int out_size) {
    const float* in[29];
    for (int i = 0; i < 29 && i < n_in; i++) in[i] = (const float*)d_in[i];

    cudaFuncSetAttribute(kA,  cudaFuncAttributeMaxDynamicSharedMemorySize, KA_SMEM);
    cudaFuncSetAttribute(kWB, cudaFuncAttributeMaxDynamicSharedMemorySize, KWB_SMEM);

    kA<<<B_*S_, 1024, KA_SMEM>>>(in[0], in[1], in[2], in[3], in[4],
                                 in[5], in[6], in[7], in[8], in[9],
                                 in[10], in[11], in[12], in[13], in[14], in[15],
                                 in[16], in[17], in[18], in[19],
                                 in[20], in[21], in[22], in[23]);
    kWB<<<B_*8, 512, KWB_SMEM>>>(in[24], in[25], in[26], in[27], in[28],
                                 (float*)d_out);
}

// round 15
// speedup vs baseline: 1.0780x; 1.0780x over previous
#include <cuda_runtime.h>

#define B_ 32
#define S_ 4
#define L_ 64
#define C_ 32
#define H_ 4
#define D_ 8
#define CP_ 16

typedef unsigned long long u64;

__device__ __forceinline__ u64 fma2(u64 a, u64 b, u64 c){
    u64 d; asm("fma.rn.f32x2 %0,%1,%2,%3;" : "=l"(d) : "l"(a),"l"(b),"l"(c)); return d;
}
__device__ __forceinline__ u64 mul2(u64 a, u64 b){
    u64 d; asm("mul.rn.f32x2 %0,%1,%2;" : "=l"(d) : "l"(a),"l"(b)); return d;
}
__device__ __forceinline__ u64 add2(u64 a, u64 b){
    u64 d; asm("add.rn.f32x2 %0,%1,%2;" : "=l"(d) : "l"(a),"l"(b)); return d;
}
__device__ __forceinline__ u64 pack2(float lo, float hi){
    u64 d; asm("mov.b64 %0,{%1,%2};" : "=l"(d) : "f"(lo),"f"(hi)); return d;
}
__device__ __forceinline__ float2 unpack2(u64 v){
    float x,y; asm("mov.b64 {%0,%1},%2;" : "=f"(x),"=f"(y) : "l"(v)); return make_float2(x,y);
}

__device__ float g_xbuf[B_*S_*L_*C_];

__device__ __forceinline__ int keyf(int r){
    return ((((r>>2)&7) ^ (((r>>5)&1)<<2)) << 2);
}
__device__ __forceinline__ int xi(int r, int c){ return r*36 + (c ^ keyf(r)); }

// ---------------------------------------------------------------------------
// Kernel A: one block per (b,s), 1024 threads. (R13 structure + early PDL
// trigger so the dependent kWB can run its pp_w prologue concurrently)
// ---------------------------------------------------------------------------
#define QSOFF 2304
#define KSOFF 4608
#define VSOFF 6912
#define GWOFF 13568
#define GBOFF 13824
#define WQ2U 6928
#define WK2U 7472
#define WV2U 8016
#define WO2U 8560
#define KA_SMEM (18208*4)
#define BKI(l,m) (9216 + (l)*68 + (m))

__global__ void __launch_bounds__(1024) kA(
    const float* __restrict__ chip0, const float* __restrict__ chip1,
    const float* __restrict__ chip2, const float* __restrict__ chip3,
    const float* __restrict__ bulk,
    const float* __restrict__ we_w, const float* __restrict__ we_b,
    const float* __restrict__ pos,
    const float* __restrict__ mn_g, const float* __restrict__ mn_b,
    const float* __restrict__ wq, const float* __restrict__ bq,
    const float* __restrict__ wk, const float* __restrict__ bk,
    const float* __restrict__ wv, const float* __restrict__ bv,
    const float* __restrict__ wo, const float* __restrict__ bo,
    const float* __restrict__ an_g, const float* __restrict__ an_b,
    const float* __restrict__ conv_w, const float* __restrict__ conv_b,
    const float* __restrict__ gate_w, const float* __restrict__ gate_b)
{
    extern __shared__ float sm[];
    u64* smu = reinterpret_cast<u64*>(sm);
    const int t = threadIdx.x;
    const int b = blockIdx.x >> 2, s = blockIdx.x & 3;
    const float* chip = (s==0)?chip0:(s==1)?chip1:(s==2)?chip2:chip3;

#if __CUDA_ARCH__ >= 900
    cudaTriggerProgrammaticLaunchCompletion();   // let kWB start its prologue
#endif

    for (int idx = t; idx < 512; idx += 1024) {
        const int r = idx >> 4, c2 = idx & 15;
        const int o = r*17 + c2;
        float2 a;
        a = *reinterpret_cast<const float2*>(&wq[idx*2]); smu[WQ2U + o] = *reinterpret_cast<u64*>(&a);
        a = *reinterpret_cast<const float2*>(&wk[idx*2]); smu[WK2U + o] = *reinterpret_cast<u64*>(&a);
        a = *reinterpret_cast<const float2*>(&wv[idx*2]); smu[WV2U + o] = *reinterpret_cast<u64*>(&a);
        a = *reinterpret_cast<const float2*>(&wo[idx*2]); smu[WO2U + o] = *reinterpret_cast<u64*>(&a);
    }
    for (int idx = t; idx < L_*L_; idx += 1024)
        sm[BKI(idx>>6, idx&63)] = bulk[b*L_*L_ + idx];
    if (t < 256) sm[GWOFF + t] = gate_w[t];
    if (t >= 256 && t < 288) sm[GBOFF + t - 256] = gate_b[t - 256];

    // phase 1: msa + pos, LN(mn). 16 threads/row.
    {
        const int l = t >> 4, q = t & 15, c0 = q*2;
        const float sig = chip[b*L_ + l];
        const float2 ww = *reinterpret_cast<const float2*>(&we_w[c0]);
        const float2 wb = *reinterpret_cast<const float2*>(&we_b[c0]);
        const float2 pp = *reinterpret_cast<const float2*>(&pos[l*C_ + c0]);
        const float v0 = fmaf(sig, ww.x, wb.x) + pp.x;
        const float v1 = fmaf(sig, ww.y, wb.y) + pp.y;
        float s1 = v0 + v1, s2 = v0*v0 + v1*v1;
        #pragma unroll
        for (int o = 1; o < 16; o <<= 1) {
            s1 += __shfl_xor_sync(0xffffffffu, s1, o);
            s2 += __shfl_xor_sync(0xffffffffu, s2, o);
        }
        const float mean = s1*(1.f/C_);
        const float rstd = rsqrtf(s2*(1.f/C_) - mean*mean + 1e-5f);
        sm[xi(l,c0)]   = (v0-mean)*rstd*mn_g[c0]   + mn_b[c0];
        sm[xi(l,c0+1)] = (v1-mean)*rstd*mn_g[c0+1] + mn_b[c0+1];
    }
    __syncthreads();

    // phase 2: QKV via f32x2/u64.
    {
        const int co = t & 31, lbase = (t >> 5) * 2;
        const int x0b = lbase*18,     k0h = keyf(lbase)   >> 1;
        const int x1b = (lbase+1)*18, k1h = keyf(lbase+1) >> 1;
        const int wrow = co*17;
        u64 aq0=0, aq1=0, ak0=0, ak1=0, av0=0, av1=0;
        #pragma unroll 8
        for (int c2 = 0; c2 < 16; c2++) {
            const u64 x0 = smu[x0b + (c2 ^ k0h)];
            const u64 x1 = smu[x1b + (c2 ^ k1h)];
            const u64 wqv = smu[WQ2U + wrow + c2];
            const u64 wkv = smu[WK2U + wrow + c2];
            const u64 wvv = smu[WV2U + wrow + c2];
            aq0 = fma2(x0, wqv, aq0); aq1 = fma2(x1, wqv, aq1);
            ak0 = fma2(x0, wkv, ak0); ak1 = fma2(x1, wkv, ak1);
            av0 = fma2(x0, wvv, av0); av1 = fma2(x1, wvv, av1);
        }
        const float ibq = bq[co], ibk = bk[co], ibv = bv[co];
        float2 f;
        f = unpack2(aq0); sm[QSOFF + xi(lbase,co)]   = f.x + f.y + ibq;
        f = unpack2(aq1); sm[QSOFF + xi(lbase+1,co)] = f.x + f.y + ibq;
        f = unpack2(ak0); sm[KSOFF + xi(lbase,co)]   = f.x + f.y + ibk;
        f = unpack2(ak1); sm[KSOFF + xi(lbase+1,co)] = f.x + f.y + ibk;
        f = unpack2(av0); sm[VSOFF + xi(lbase,co)]   = f.x + f.y + ibv;
        f = unpack2(av1); sm[VSOFF + xi(lbase+1,co)] = f.x + f.y + ibv;
    }
    __syncthreads();

    // phase 3: attention (interleaved m = 4*mm + quarter); gate split 4-ways.
    {
        const int h = t >> 8, rem = t & 255;
        const int l = rem >> 2, quarter = rem & 3;
        const int hc = h*D_;
        const float rsd = 0.35355339059327373f;

        ulonglong2 qa = *reinterpret_cast<const ulonglong2*>(&sm[QSOFF + xi(l,hc)]);
        ulonglong2 qb = *reinterpret_cast<const ulonglong2*>(&sm[QSOFF + xi(l,hc+4)]);
        const u64 rsd2 = pack2(rsd, rsd);
        qa.x = mul2(qa.x, rsd2); qa.y = mul2(qa.y, rsd2);
        qb.x = mul2(qb.x, rsd2); qb.y = mul2(qb.y, rsd2);
        const float cw = conv_w[h], cb = conv_b[h];

        float Z = 0.f;
        u64 A0 = 0ull, A1 = 0ull, A2 = 0ull, A3 = 0ull;

        #pragma unroll 4
        for (int mm = 0; mm < 16; mm++) {
            const int m = mm*4 + quarter;
            const ulonglong2 ka = *reinterpret_cast<const ulonglong2*>(&sm[KSOFF + xi(m,hc)]);
            const ulonglong2 kb = *reinterpret_cast<const ulonglong2*>(&sm[KSOFF + xi(m,hc+4)]);
            u64 u = mul2(qa.x, ka.x);
            u = fma2(qa.y, ka.y, u);
            u = fma2(qb.x, kb.x, u);
            u = fma2(qb.y, kb.y, u);
            const float2 uf = unpack2(u);
            const float sc = uf.x + uf.y + fmaf(sm[BKI(l,m)], cw, cb);
            const float p = __expf(sc);
            Z += p;
            const u64 pp = pack2(p, p);
            const ulonglong2 va = *reinterpret_cast<const ulonglong2*>(&sm[VSOFF + xi(m,hc)]);
            const ulonglong2 vb = *reinterpret_cast<const ulonglong2*>(&sm[VSOFF + xi(m,hc+4)]);
            A0 = fma2(pp, va.x, A0); A1 = fma2(pp, va.y, A1);
            A2 = fma2(pp, vb.x, A2); A3 = fma2(pp, vb.y, A3);
        }
        #pragma unroll
        for (int o = 1; o < 4; o <<= 1) {
            Z  += __shfl_xor_sync(0xffffffffu, Z, o);
            A0 = add2(A0, __shfl_xor_sync(0xffffffffu, A0, o));
            A1 = add2(A1, __shfl_xor_sync(0xffffffffu, A1, o));
            A2 = add2(A2, __shfl_xor_sync(0xffffffffu, A2, o));
            A3 = add2(A3, __shfl_xor_sync(0xffffffffu, A3, o));
        }

        const float inv = 1.f/Z;
        const float2 f0 = unpack2(A0), f1 = unpack2(A1), f2 = unpack2(A2), f3 = unpack2(A3);
        float o[D_];
        o[0]=f0.x*inv; o[1]=f0.y*inv; o[2]=f1.x*inv; o[3]=f1.y*inv;
        o[4]=f2.x*inv; o[5]=f2.y*inv; o[6]=f3.x*inv; o[7]=f3.y*inv;
        const int d0 = quarter*2;
        float2 og;
        #pragma unroll
        for (int k = 0; k < 2; k++) {
            const int d = d0 + k;
            const float4 w0 = *reinterpret_cast<const float4*>(&sm[GWOFF + h*64 + d*8]);
            const float4 w1 = *reinterpret_cast<const float4*>(&sm[GWOFF + h*64 + d*8 + 4]);
            float g = sm[GBOFF + hc + d];
            g += w0.x*o[0] + w0.y*o[1] + w0.z*o[2] + w0.w*o[3];
            g += w1.x*o[4] + w1.y*o[5] + w1.z*o[6] + w1.w*o[7];
            (&og.x)[k] = __fdividef(o[d], 1.f + __expf(-g));
        }
        __syncthreads();
        *reinterpret_cast<float2*>(&sm[QSOFF + xi(l, hc + d0)]) = og;
    }
    __syncthreads();

    // phase 4: wo + residual + LN(an) fused -> g_xbuf.
    {
        const int co = t & 31, lbase = (t >> 5) * 2;
        const int x0b = lbase*18,     k0h = keyf(lbase)   >> 1;
        const int x1b = (lbase+1)*18, k1h = keyf(lbase+1) >> 1;
        const int wrow = co*17;
        u64 a0 = 0, a1 = 0;
        #pragma unroll 8
        for (int c2 = 0; c2 < 16; c2++) {
            const u64 w = smu[WO2U + wrow + c2];
            a0 = fma2(smu[(QSOFF>>1) + x0b + (c2 ^ k0h)], w, a0);
            a1 = fma2(smu[(QSOFF>>1) + x1b + (c2 ^ k1h)], w, a1);
        }
        const float ib = bo[co];
        const float2 fa = unpack2(a0), fb = unpack2(a1);
        const float v0 = sm[xi(lbase,co)]   + fa.x + fa.y + ib;
        const float v1 = sm[xi(lbase+1,co)] + fb.x + fb.y + ib;

        u64 S1 = pack2(v0, v1), S2 = pack2(v0*v0, v1*v1);
        #pragma unroll
        for (int o = 1; o < 32; o <<= 1) {
            S1 = add2(S1, __shfl_xor_sync(0xffffffffu, S1, o));
            S2 = add2(S2, __shfl_xor_sync(0xffffffffu, S2, o));
        }
        const float2 s1 = unpack2(S1), s2 = unpack2(S2);
        const float m0 = s1.x*(1.f/C_), m1 = s1.y*(1.f/C_);
        const float r0 = rsqrtf(s2.x*(1.f/C_) - m0*m0 + 1e-5f);
        const float r1 = rsqrtf(s2.y*(1.f/C_) - m1*m1 + 1e-5f);
        const float ag = an_g[co], ab = an_b[co];
        float* dst = g_xbuf + ((b*S_ + s)*L_ + lbase)*C_ + co;
        dst[0]   = (v0 - m0)*r0*ag + ab;
        dst[C_]  = (v1 - m1)*r1*ag + ab;
    }
}

// ---------------------------------------------------------------------------
// Kernel kWB (R13 v3 + PDL prologue): grid = (b, i-group-of-16) = 128 blocks,
// 512 threads. pp_w is staged to smem BEFORE cudaGridDependencySynchronize(),
// overlapping the fetch + launch latency with kA's execution.
// smem floats: MT@0 (32c x 68j = 2176), WIT@2176 (16ii x 32d x 20p = 10240),
// RNV@12416 (64), PWS@12480 (16p x 1028 = 16448). Total 28928 fl = 115712 B.
// ---------------------------------------------------------------------------
#define MT   0
#define WIT  2176
#define RNV  12416
#define PWS  12480
#define KWB_SMEM (28928*4)

__global__ void __launch_bounds__(512) kWB(
    const float* __restrict__ pp_w, const float* __restrict__ pp_b,
    const float* __restrict__ ada_g, const float* __restrict__ ada_b,
    const float* __restrict__ ada_alpha, float* __restrict__ out)
{
    extern __shared__ float smw[];
    const int t = threadIdx.x;
    const int b = blockIdx.x >> 2, i0 = (blockIdx.x & 3) * 16;
    const float* xb = g_xbuf + b*S_*L_*C_;

    // prologue (independent of kA): stage pp_w -> smem, rows padded to 1028.
    for (int idx = t; idx < 4096; idx += 512) {
        const int p = idx >> 8, c4 = idx & 255;
        *reinterpret_cast<float4*>(&smw[PWS + p*1028 + c4*4]) =
            *reinterpret_cast<const float4*>(&pp_w[p*1024 + c4*4]);
    }

#if __CUDA_ARCH__ >= 900
    cudaGridDependencySynchronize();   // wait for kA's g_xbuf
#endif

    // phase 1: max over tracks -> mT[c][j] (transposed)
    for (int idx = t; idx < L_*C_; idx += 512) {
        const int j = idx >> 5, c = idx & 31;
        const float m = fmaxf(fmaxf(xb[idx], xb[2048+idx]),
                              fmaxf(xb[4096+idx], xb[6144+idx]));
        smw[MT + c*68 + j] = m;
    }
    __syncthreads();

    // phase 2: rinv per j
    if (t < L_) {
        float ss = 0.f;
        #pragma unroll
        for (int c = 0; c < C_; c++) { const float v = smw[MT + c*68 + t]; ss += v*v; }
        smw[RNV + t] = rsqrtf(ss);
    }
    __syncthreads();

    // phase 3: normalize mT
    for (int idx = t; idx < L_*C_; idx += 512) {
        const int j = idx & 63, c = idx >> 6;
        smw[MT + c*68 + j] *= smw[RNV + j];
    }
    __syncthreads();

    // phase 4: wi. warp = p, lane = d; W_p column from PWS (banks 4p+d, CF);
    // stores use p-XOR key for conflict-free WIT.
    {
        const int p = t >> 5, d = t & 31;
        const int pk = p ^ (((d >> 3) & 3) << 2);
        u64 acc[8];
        #pragma unroll
        for (int k = 0; k < 8; k++) acc[k] = 0ull;
        #pragma unroll 4
        for (int c = 0; c < 32; c++) {
            const float wv = smw[PWS + p*1028 + c*32 + d];
            const float* mb = &smw[MT + c*68 + i0];
            const ulonglong2 ma = *reinterpret_cast<const ulonglong2*>(mb);
            const ulonglong2 mbv = *reinterpret_cast<const ulonglong2*>(mb+4);
            const ulonglong2 mc = *reinterpret_cast<const ulonglong2*>(mb+8);
            const ulonglong2 md = *reinterpret_cast<const ulonglong2*>(mb+12);
            const u64 w2 = pack2(wv, wv);
            acc[0] = fma2(ma.x,  w2, acc[0]); acc[1] = fma2(ma.y,  w2, acc[1]);
            acc[2] = fma2(mbv.x, w2, acc[2]); acc[3] = fma2(mbv.y, w2, acc[3]);
            acc[4] = fma2(mc.x,  w2, acc[4]); acc[5] = fma2(mc.y,  w2, acc[5]);
            acc[6] = fma2(md.x,  w2, acc[6]); acc[7] = fma2(md.y,  w2, acc[7]);
        }
        #pragma unroll
        for (int k = 0; k < 8; k++) {
            const float2 f = unpack2(acc[k]);
            smw[WIT + (2*k)*640   + d*20 + pk] = f.x;
            smw[WIT + (2*k+1)*640 + d*20 + pk] = f.y;
        }
    }
    __syncthreads();

    // phase 5: pair gemm + AdaNorm + SiLU. warp -> (ii, jhalf); lane = j.
    // 2 passes over ii (+8). Fully unrolled; chunk u feeds p-group u^kk.
    {
        const int w = t >> 5, lane = t & 31;
        const int jj = (w & 1)*32 + lane;
        const float alpha = ada_alpha[0];

        #pragma unroll
        for (int pass = 0; pass < 2; pass++) {
            const int ii = (w >> 1) + 8*pass;
            const int i = i0 + ii;

            u64 acc[8];
            #pragma unroll
            for (int k = 0; k < 8; k++) acc[k] = 0ull;

            #pragma unroll
            for (int c = 0; c < 32; c++) {
                const int kk = (c >> 3) & 3;
                const float mj = smw[MT + c*68 + jj];
                const u64 m2 = pack2(mj, mj);
                const float* wb = &smw[WIT + ii*640 + c*20];
                ulonglong2 wv[4];
                wv[0] = *reinterpret_cast<const ulonglong2*>(wb);
                wv[1] = *reinterpret_cast<const ulonglong2*>(wb+4);
                wv[2] = *reinterpret_cast<const ulonglong2*>(wb+8);
                wv[3] = *reinterpret_cast<const ulonglong2*>(wb+12);
                #pragma unroll
                for (int u = 0; u < 4; u++) {
                    const int g = u ^ kk;
                    acc[2*g]   = fma2(wv[u].x, m2, acc[2*g]);
                    acc[2*g+1] = fma2(wv[u].y, m2, acc[2*g+1]);
                }
            }

            float feat[16];
            float s1 = 0.f, s2 = 0.f;
            #pragma unroll
            for (int k = 0; k < 8; k++) {
                const float2 f = unpack2(acc[k]);
                const float v0 = f.x + pp_b[2*k];
                const float v1 = f.y + pp_b[2*k+1];
                feat[2*k] = v0; feat[2*k+1] = v1;
                s1 += v0 + v1; s2 += v0*v0 + v1*v1;
            }
            const float mu = s1*(1.f/CP_);
            const float rstd = rsqrtf(s2*(1.f/CP_) - mu*mu + 1e-5f);

            #pragma unroll
            for (int p = 0; p < CP_; p++) {
                const float v = feat[p];
                const float ln = (v - mu)*rstd*ada_g[p] + ada_b[p];
                const float val = v + alpha*ln;
                out[((b*CP_ + p)*L_ + i)*L_ + jj] =
                    __fdividef(val, 1.f + __expf(-val));
            }
        }
    }
}

extern "C" void kernel_launch(void* const* d_in, const int* in_sizes, int n_in,
                              void* d_out, int out_size) {
    const float* in[29];
    for (int i = 0; i < 29 && i < n_in; i++) in[i] = (const float*)d_in[i];

    cudaFuncSetAttribute(kA,  cudaFuncAttributeMaxDynamicSharedMemorySize, KA_SMEM);
    cudaFuncSetAttribute(kWB, cudaFuncAttributeMaxDynamicSharedMemorySize, KWB_SMEM);

    kA<<<B_*S_, 1024, KA_SMEM>>>(in[0], in[1], in[2], in[3], in[4],
                                 in[5], in[6], in[7], in[8], in[9],
                                 in[10], in[11], in[12], in[13], in[14], in[15],
                                 in[16], in[17], in[18], in[19],
                                 in[20], in[21], in[22], in[23]);

    // kWB with programmatic dependent launch: prologue overlaps kA.
    cudaLaunchConfig_t cfg = {};
    cfg.gridDim = dim3(B_*4);
    cfg.blockDim = dim3(512);
    cfg.dynamicSmemBytes = KWB_SMEM;
    cfg.stream = 0;
    cudaLaunchAttribute attrs[1];
    attrs[0].id = cudaLaunchAttributeProgrammaticStreamSerialization;
    attrs[0].val.programmaticStreamSerializationAllowed = 1;
    cfg.attrs = attrs;
    cfg.numAttrs = 1;

    float* outp = (float*)d_out;
    cudaLaunchKernelEx(&cfg, kWB, in[24], in[25], in[26], in[27], in[28], outp);
}

// round 16
// speedup vs baseline: 1.1273x; 1.0457x over previous
#include <cuda_runtime.h>

#define B_ 32
#define S_ 4
#define L_ 64
#define C_ 32
#define H_ 4
#define D_ 8
#define CP_ 16

typedef unsigned long long u64;

__device__ __forceinline__ u64 fma2(u64 a, u64 b, u64 c){
    u64 d; asm("fma.rn.f32x2 %0,%1,%2,%3;" : "=l"(d) : "l"(a),"l"(b),"l"(c)); return d;
}
__device__ __forceinline__ u64 mul2(u64 a, u64 b){
    u64 d; asm("mul.rn.f32x2 %0,%1,%2;" : "=l"(d) : "l"(a),"l"(b)); return d;
}
__device__ __forceinline__ u64 add2(u64 a, u64 b){
    u64 d; asm("add.rn.f32x2 %0,%1,%2;" : "=l"(d) : "l"(a),"l"(b)); return d;
}
__device__ __forceinline__ u64 pack2(float lo, float hi){
    u64 d; asm("mov.b64 %0,{%1,%2};" : "=l"(d) : "f"(lo),"f"(hi)); return d;
}
__device__ __forceinline__ float2 unpack2(u64 v){
    float x,y; asm("mov.b64 {%0,%1},%2;" : "=f"(x),"=f"(y) : "l"(v)); return make_float2(x,y);
}

__device__ float g_xbuf[B_*S_*L_*C_];

__device__ __forceinline__ int keyf(int r){
    return ((((r>>2)&7) ^ (((r>>5)&1)<<2)) << 2);
}
__device__ __forceinline__ int xi(int r, int c){ return r*36 + (c ^ keyf(r)); }
__device__ __forceinline__ int swz(int r, int c){ return r*36 + (c ^ (((r>>2)&7)<<2)); }

// ---------------------------------------------------------------------------
// Kernel A: one block per (b,s), 1024 threads. (frozen R13, 17.2us)
// ---------------------------------------------------------------------------
#define QSOFF 2304
#define KSOFF 4608
#define VSOFF 6912
#define GWOFF 13568
#define GBOFF 13824
#define WQ2U 6928
#define WK2U 7472
#define WV2U 8016
#define WO2U 8560
#define KA_SMEM (18208*4)
#define BKI(l,m) (9216 + (l)*68 + (m))

__global__ void __launch_bounds__(1024) kA(
    const float* __restrict__ chip0, const float* __restrict__ chip1,
    const float* __restrict__ chip2, const float* __restrict__ chip3,
    const float* __restrict__ bulk,
    const float* __restrict__ we_w, const float* __restrict__ we_b,
    const float* __restrict__ pos,
    const float* __restrict__ mn_g, const float* __restrict__ mn_b,
    const float* __restrict__ wq, const float* __restrict__ bq,
    const float* __restrict__ wk, const float* __restrict__ bk,
    const float* __restrict__ wv, const float* __restrict__ bv,
    const float* __restrict__ wo, const float* __restrict__ bo,
    const float* __restrict__ an_g, const float* __restrict__ an_b,
    const float* __restrict__ conv_w, const float* __restrict__ conv_b,
    const float* __restrict__ gate_w, const float* __restrict__ gate_b)
{
    extern __shared__ float sm[];
    u64* smu = reinterpret_cast<u64*>(sm);
    const int t = threadIdx.x;
    const int b = blockIdx.x >> 2, s = blockIdx.x & 3;
    const float* chip = (s==0)?chip0:(s==1)?chip1:(s==2)?chip2:chip3;

    for (int idx = t; idx < 512; idx += 1024) {
        const int r = idx >> 4, c2 = idx & 15;
        const int o = r*17 + c2;
        float2 a;
        a = *reinterpret_cast<const float2*>(&wq[idx*2]); smu[WQ2U + o] = *reinterpret_cast<u64*>(&a);
        a = *reinterpret_cast<const float2*>(&wk[idx*2]); smu[WK2U + o] = *reinterpret_cast<u64*>(&a);
        a = *reinterpret_cast<const float2*>(&wv[idx*2]); smu[WV2U + o] = *reinterpret_cast<u64*>(&a);
        a = *reinterpret_cast<const float2*>(&wo[idx*2]); smu[WO2U + o] = *reinterpret_cast<u64*>(&a);
    }
    for (int idx = t; idx < L_*L_; idx += 1024)
        sm[BKI(idx>>6, idx&63)] = bulk[b*L_*L_ + idx];
    if (t < 256) sm[GWOFF + t] = gate_w[t];
    if (t >= 256 && t < 288) sm[GBOFF + t - 256] = gate_b[t - 256];

    // phase 1
    {
        const int l = t >> 4, q = t & 15, c0 = q*2;
        const float sig = chip[b*L_ + l];
        const float2 ww = *reinterpret_cast<const float2*>(&we_w[c0]);
        const float2 wb = *reinterpret_cast<const float2*>(&we_b[c0]);
        const float2 pp = *reinterpret_cast<const float2*>(&pos[l*C_ + c0]);
        const float v0 = fmaf(sig, ww.x, wb.x) + pp.x;
        const float v1 = fmaf(sig, ww.y, wb.y) + pp.y;
        float s1 = v0 + v1, s2 = v0*v0 + v1*v1;
        #pragma unroll
        for (int o = 1; o < 16; o <<= 1) {
            s1 += __shfl_xor_sync(0xffffffffu, s1, o);
            s2 += __shfl_xor_sync(0xffffffffu, s2, o);
        }
        const float mean = s1*(1.f/C_);
        const float rstd = rsqrtf(s2*(1.f/C_) - mean*mean + 1e-5f);
        sm[xi(l,c0)]   = (v0-mean)*rstd*mn_g[c0]   + mn_b[c0];
        sm[xi(l,c0+1)] = (v1-mean)*rstd*mn_g[c0+1] + mn_b[c0+1];
    }
    __syncthreads();

    // phase 2
    {
        const int co = t & 31, lbase = (t >> 5) * 2;
        const int x0b = lbase*18,     k0h = keyf(lbase)   >> 1;
        const int x1b = (lbase+1)*18, k1h = keyf(lbase+1) >> 1;
        const int wrow = co*17;
        u64 aq0=0, aq1=0, ak0=0, ak1=0, av0=0, av1=0;
        #pragma unroll 8
        for (int c2 = 0; c2 < 16; c2++) {
            const u64 x0 = smu[x0b + (c2 ^ k0h)];
            const u64 x1 = smu[x1b + (c2 ^ k1h)];
            const u64 wqv = smu[WQ2U + wrow + c2];
            const u64 wkv = smu[WK2U + wrow + c2];
            const u64 wvv = smu[WV2U + wrow + c2];
            aq0 = fma2(x0, wqv, aq0); aq1 = fma2(x1, wqv, aq1);
            ak0 = fma2(x0, wkv, ak0); ak1 = fma2(x1, wkv, ak1);
            av0 = fma2(x0, wvv, av0); av1 = fma2(x1, wvv, av1);
        }
        const float ibq = bq[co], ibk = bk[co], ibv = bv[co];
        float2 f;
        f = unpack2(aq0); sm[QSOFF + xi(lbase,co)]   = f.x + f.y + ibq;
        f = unpack2(aq1); sm[QSOFF + xi(lbase+1,co)] = f.x + f.y + ibq;
        f = unpack2(ak0); sm[KSOFF + xi(lbase,co)]   = f.x + f.y + ibk;
        f = unpack2(ak1); sm[KSOFF + xi(lbase+1,co)] = f.x + f.y + ibk;
        f = unpack2(av0); sm[VSOFF + xi(lbase,co)]   = f.x + f.y + ibv;
        f = unpack2(av1); sm[VSOFF + xi(lbase+1,co)] = f.x + f.y + ibv;
    }
    __syncthreads();

    // phase 3
    {
        const int h = t >> 8, rem = t & 255;
        const int l = rem >> 2, quarter = rem & 3;
        const int hc = h*D_;
        const float rsd = 0.35355339059327373f;

        ulonglong2 qa = *reinterpret_cast<const ulonglong2*>(&sm[QSOFF + xi(l,hc)]);
        ulonglong2 qb = *reinterpret_cast<const ulonglong2*>(&sm[QSOFF + xi(l,hc+4)]);
        const u64 rsd2 = pack2(rsd, rsd);
        qa.x = mul2(qa.x, rsd2); qa.y = mul2(qa.y, rsd2);
        qb.x = mul2(qb.x, rsd2); qb.y = mul2(qb.y, rsd2);
        const float cw = conv_w[h], cb = conv_b[h];

        float Z = 0.f;
        u64 A0 = 0ull, A1 = 0ull, A2 = 0ull, A3 = 0ull;

        #pragma unroll 4
        for (int mm = 0; mm < 16; mm++) {
            const int m = mm*4 + quarter;
            const ulonglong2 ka = *reinterpret_cast<const ulonglong2*>(&sm[KSOFF + xi(m,hc)]);
            const ulonglong2 kb = *reinterpret_cast<const ulonglong2*>(&sm[KSOFF + xi(m,hc+4)]);
            u64 u = mul2(qa.x, ka.x);
            u = fma2(qa.y, ka.y, u);
            u = fma2(qb.x, kb.x, u);
            u = fma2(qb.y, kb.y, u);
            const float2 uf = unpack2(u);
            const float sc = uf.x + uf.y + fmaf(sm[BKI(l,m)], cw, cb);
            const float p = __expf(sc);
            Z += p;
            const u64 pp = pack2(p, p);
            const ulonglong2 va = *reinterpret_cast<const ulonglong2*>(&sm[VSOFF + xi(m,hc)]);
            const ulonglong2 vb = *reinterpret_cast<const ulonglong2*>(&sm[VSOFF + xi(m,hc+4)]);
            A0 = fma2(pp, va.x, A0); A1 = fma2(pp, va.y, A1);
            A2 = fma2(pp, vb.x, A2); A3 = fma2(pp, vb.y, A3);
        }
        #pragma unroll
        for (int o = 1; o < 4; o <<= 1) {
            Z  += __shfl_xor_sync(0xffffffffu, Z, o);
            A0 = add2(A0, __shfl_xor_sync(0xffffffffu, A0, o));
            A1 = add2(A1, __shfl_xor_sync(0xffffffffu, A1, o));
            A2 = add2(A2, __shfl_xor_sync(0xffffffffu, A2, o));
            A3 = add2(A3, __shfl_xor_sync(0xffffffffu, A3, o));
        }

        const float inv = 1.f/Z;
        const float2 f0 = unpack2(A0), f1 = unpack2(A1), f2 = unpack2(A2), f3 = unpack2(A3);
        float o[D_];
        o[0]=f0.x*inv; o[1]=f0.y*inv; o[2]=f1.x*inv; o[3]=f1.y*inv;
        o[4]=f2.x*inv; o[5]=f2.y*inv; o[6]=f3.x*inv; o[7]=f3.y*inv;
        const int d0 = quarter*2;
        float2 og;
        #pragma unroll
        for (int k = 0; k < 2; k++) {
            const int d = d0 + k;
            const float4 w0 = *reinterpret_cast<const float4*>(&sm[GWOFF + h*64 + d*8]);
            const float4 w1 = *reinterpret_cast<const float4*>(&sm[GWOFF + h*64 + d*8 + 4]);
            float g = sm[GBOFF + hc + d];
            g += w0.x*o[0] + w0.y*o[1] + w0.z*o[2] + w0.w*o[3];
            g += w1.x*o[4] + w1.y*o[5] + w1.z*o[6] + w1.w*o[7];
            (&og.x)[k] = __fdividef(o[d], 1.f + __expf(-g));
        }
        __syncthreads();
        *reinterpret_cast<float2*>(&sm[QSOFF + xi(l, hc + d0)]) = og;
    }
    __syncthreads();

    // phase 4
    {
        const int co = t & 31, lbase = (t >> 5) * 2;
        const int x0b = lbase*18,     k0h = keyf(lbase)   >> 1;
        const int x1b = (lbase+1)*18, k1h = keyf(lbase+1) >> 1;
        const int wrow = co*17;
        u64 a0 = 0, a1 = 0;
        #pragma unroll 8
        for (int c2 = 0; c2 < 16; c2++) {
            const u64 w = smu[WO2U + wrow + c2];
            a0 = fma2(smu[(QSOFF>>1) + x0b + (c2 ^ k0h)], w, a0);
            a1 = fma2(smu[(QSOFF>>1) + x1b + (c2 ^ k1h)], w, a1);
        }
        const float ib = bo[co];
        const float2 fa = unpack2(a0), fb = unpack2(a1);
        const float v0 = sm[xi(lbase,co)]   + fa.x + fa.y + ib;
        const float v1 = sm[xi(lbase+1,co)] + fb.x + fb.y + ib;

        u64 S1 = pack2(v0, v1), S2 = pack2(v0*v0, v1*v1);
        #pragma unroll
        for (int o = 1; o < 32; o <<= 1) {
            S1 = add2(S1, __shfl_xor_sync(0xffffffffu, S1, o));
            S2 = add2(S2, __shfl_xor_sync(0xffffffffu, S2, o));
        }
        const float2 s1 = unpack2(S1), s2 = unpack2(S2);
        const float m0 = s1.x*(1.f/C_), m1 = s1.y*(1.f/C_);
        const float r0 = rsqrtf(s2.x*(1.f/C_) - m0*m0 + 1e-5f);
        const float r1 = rsqrtf(s2.y*(1.f/C_) - m1*m1 + 1e-5f);
        const float ag = an_g[co], ab = an_b[co];
        float* dst = g_xbuf + ((b*S_ + s)*L_ + lbase)*C_ + co;
        dst[0]   = (v0 - m0)*r0*ag + ab;
        dst[C_]  = (v1 - m1)*r1*ag + ab;
    }
}

// ---------------------------------------------------------------------------
// Kernel kWB (R13 + MJ transposed tile + smem-staged epilogue params):
// grid = (b, i-group-of-16) = 128 blocks, 512 threads.
// smem floats: MT@0 (32c x 68j = 2176), WIT@2176 (10240), RNV@12416 (64),
// MJ@12480 (64j x 36c swz = 2304), PRM@14784 (49).  Total 14840 fl = 59360 B.
// ---------------------------------------------------------------------------
#define MT   0
#define WIT  2176
#define RNV  12416
#define MJ   12480
#define PRM  14784
#define KWB_SMEM (14840*4)

__global__ void __launch_bounds__(512) kWB(
    const float* __restrict__ pp_w, const float* __restrict__ pp_b,
    const float* __restrict__ ada_g, const float* __restrict__ ada_b,
    const float* __restrict__ ada_alpha, float* __restrict__ out)
{
    extern __shared__ float smw[];
    const int t = threadIdx.x;
    const int b = blockIdx.x >> 2, i0 = (blockIdx.x & 3) * 16;
    const float* xb = g_xbuf + b*S_*L_*C_;

    // stage epilogue params once
    if (t < CP_)                smw[PRM + t]          = pp_b[t];
    else if (t < 2*CP_)         smw[PRM + t]          = ada_g[t - CP_];
    else if (t < 3*CP_)         smw[PRM + t]          = ada_b[t - 2*CP_];
    else if (t == 3*CP_)        smw[PRM + 48]         = ada_alpha[0];

    // phase 1: max over tracks -> mT[c][j]
    for (int idx = t; idx < L_*C_; idx += 512) {
        const int j = idx >> 5, c = idx & 31;
        const float m = fmaxf(fmaxf(xb[idx], xb[2048+idx]),
                              fmaxf(xb[4096+idx], xb[6144+idx]));
        smw[MT + c*68 + j] = m;
    }
    __syncthreads();

    // phase 2: rinv per j
    if (t < L_) {
        float ss = 0.f;
        #pragma unroll
        for (int c = 0; c < C_; c++) { const float v = smw[MT + c*68 + t]; ss += v*v; }
        smw[RNV + t] = rsqrtf(ss);
    }
    __syncthreads();

    // phase 3: normalize mT; also write transposed MJ[j][c] (swz, CF stores)
    for (int idx = t; idx < L_*C_; idx += 512) {
        const int j = idx & 63, c = idx >> 6;
        const float v = smw[MT + c*68 + j] * smw[RNV + j];
        smw[MT + c*68 + j] = v;
        smw[MJ + swz(j, c)] = v;
    }
    __syncthreads();

    // phase 4: wi. warp = p, lane = d; pp_w column in regs; WIT p-XOR key.
    {
        const int p = t >> 5, d = t & 31;
        const int pk = p ^ (((d >> 3) & 3) << 2);
        float wreg[32];
        #pragma unroll
        for (int c = 0; c < 32; c++) wreg[c] = pp_w[p*1024 + c*32 + d];
        u64 acc[8];
        #pragma unroll
        for (int k = 0; k < 8; k++) acc[k] = 0ull;
        #pragma unroll 4
        for (int c = 0; c < 32; c++) {
            const float* mb = &smw[MT + c*68 + i0];
            const ulonglong2 ma = *reinterpret_cast<const ulonglong2*>(mb);
            const ulonglong2 mbv = *reinterpret_cast<const ulonglong2*>(mb+4);
            const ulonglong2 mc = *reinterpret_cast<const ulonglong2*>(mb+8);
            const ulonglong2 md = *reinterpret_cast<const ulonglong2*>(mb+12);
            const u64 w2 = pack2(wreg[c], wreg[c]);
            acc[0] = fma2(ma.x,  w2, acc[0]); acc[1] = fma2(ma.y,  w2, acc[1]);
            acc[2] = fma2(mbv.x, w2, acc[2]); acc[3] = fma2(mbv.y, w2, acc[3]);
            acc[4] = fma2(mc.x,  w2, acc[4]); acc[5] = fma2(mc.y,  w2, acc[5]);
            acc[6] = fma2(md.x,  w2, acc[6]); acc[7] = fma2(md.y,  w2, acc[7]);
        }
        #pragma unroll
        for (int k = 0; k < 8; k++) {
            const float2 f = unpack2(acc[k]);
            smw[WIT + (2*k)*640   + d*20 + pk] = f.x;
            smw[WIT + (2*k+1)*640 + d*20 + pk] = f.y;
        }
    }
    __syncthreads();

    // phase 5: pair gemm + AdaNorm + SiLU. warp -> (ii, jhalf); lane = j.
    // mj via conflict-free LDS.128 from MJ; chunk u feeds p-group u^kk.
    {
        const int w = t >> 5, lane = t & 31;
        const int jj = (w & 1)*32 + lane;
        const float alpha = smw[PRM + 48];

        #pragma unroll
        for (int pass = 0; pass < 2; pass++) {
            const int ii = (w >> 1) + 8*pass;
            const int i = i0 + ii;

            u64 acc[8];
            #pragma unroll
            for (int k = 0; k < 8; k++) acc[k] = 0ull;

            #pragma unroll
            for (int cg = 0; cg < 8; cg++) {
                const float4 mj4 = *reinterpret_cast<const float4*>(&smw[MJ + swz(jj, cg*4)]);
                #pragma unroll
                for (int cc = 0; cc < 4; cc++) {
                    const int c = cg*4 + cc;
                    const int kk = (c >> 3) & 3;
                    const u64 m2 = pack2((&mj4.x)[cc], (&mj4.x)[cc]);
                    const float* wb = &smw[WIT + ii*640 + c*20];
                    ulonglong2 wv[4];
                    wv[0] = *reinterpret_cast<const ulonglong2*>(wb);
                    wv[1] = *reinterpret_cast<const ulonglong2*>(wb+4);
                    wv[2] = *reinterpret_cast<const ulonglong2*>(wb+8);
                    wv[3] = *reinterpret_cast<const ulonglong2*>(wb+12);
                    #pragma unroll
                    for (int u = 0; u < 4; u++) {
                        const int g = u ^ kk;
                        acc[2*g]   = fma2(wv[u].x, m2, acc[2*g]);
                        acc[2*g+1] = fma2(wv[u].y, m2, acc[2*g+1]);
                    }
                }
            }

            float feat[16];
            float s1 = 0.f, s2 = 0.f;
            #pragma unroll
            for (int k = 0; k < 8; k++) {
                const float2 f = unpack2(acc[k]);
                const float v0 = f.x + smw[PRM + 2*k];
                const float v1 = f.y + smw[PRM + 2*k+1];
                feat[2*k] = v0; feat[2*k+1] = v1;
                s1 += v0 + v1; s2 += v0*v0 + v1*v1;
            }
            const float mu = s1*(1.f/CP_);
            const float rstd = rsqrtf(s2*(1.f/CP_) - mu*mu + 1e-5f);

            #pragma unroll
            for (int p = 0; p < CP_; p++) {
                const float v = feat[p];
                const float ln = (v - mu)*rstd*smw[PRM + 16 + p] + smw[PRM + 32 + p];
                const float val = v + alpha*ln;
                out[((b*CP_ + p)*L_ + i)*L_ + jj] =
                    __fdividef(val, 1.f + __expf(-val));
            }
        }
    }
}

extern "C" void kernel_launch(void* const* d_in, const int* in_sizes, int n_in,
                              void* d_out, int out_size) {
    const float* in[29];
    for (int i = 0; i < 29 && i < n_in; i++) in[i] = (const float*)d_in[i];

    cudaFuncSetAttribute(kA,  cudaFuncAttributeMaxDynamicSharedMemorySize, KA_SMEM);
    cudaFuncSetAttribute(kWB, cudaFuncAttributeMaxDynamicSharedMemorySize, KWB_SMEM);

    kA<<<B_*S_, 1024, KA_SMEM>>>(in[0], in[1], in[2], in[3], in[4],
                                 in[5], in[6], in[7], in[8], in[9],
                                 in[10], in[11], in[12], in[13], in[14], in[15],
                                 in[16], in[17], in[18], in[19],
                                 in[20], in[21], in[22], in[23]);
    kWB<<<B_*4, 512, KWB_SMEM>>>(in[24], in[25], in[26], in[27], in[28],
                                 (float*)d_out);
}

// round 17
// speedup vs baseline: 1.2217x; 1.0837x over previous
#include <cuda_runtime.h>

#define B_ 32
#define S_ 4
#define L_ 64
#define C_ 32
#define H_ 4
#define D_ 8
#define CP_ 16

typedef unsigned long long u64;

__device__ __forceinline__ u64 fma2(u64 a, u64 b, u64 c){
    u64 d; asm("fma.rn.f32x2 %0,%1,%2,%3;" : "=l"(d) : "l"(a),"l"(b),"l"(c)); return d;
}
__device__ __forceinline__ u64 mul2(u64 a, u64 b){
    u64 d; asm("mul.rn.f32x2 %0,%1,%2;" : "=l"(d) : "l"(a),"l"(b)); return d;
}
__device__ __forceinline__ u64 add2(u64 a, u64 b){
    u64 d; asm("add.rn.f32x2 %0,%1,%2;" : "=l"(d) : "l"(a),"l"(b)); return d;
}
__device__ __forceinline__ u64 pack2(float lo, float hi){
    u64 d; asm("mov.b64 %0,{%1,%2};" : "=l"(d) : "f"(lo),"f"(hi)); return d;
}
__device__ __forceinline__ float2 unpack2(u64 v){
    float x,y; asm("mov.b64 {%0,%1},%2;" : "=f"(x),"=f"(y) : "l"(v)); return make_float2(x,y);
}
__device__ __forceinline__ float sigmoid_t(float x){
    float t; asm("tanh.approx.f32 %0, %1;" : "=f"(t) : "f"(x*0.5f));
    return 0.5f*t + 0.5f;
}

__device__ float g_xbuf[B_*S_*L_*C_];

__device__ __forceinline__ int keyf(int r){
    return ((((r>>2)&7) ^ (((r>>5)&1)<<2)) << 2);
}
__device__ __forceinline__ int xi(int r, int c){ return r*36 + (c ^ keyf(r)); }

// ---------------------------------------------------------------------------
// Kernel A: one block per (b,s), 1024 threads. (R13 structure; tanh gate)
// ---------------------------------------------------------------------------
#define QSOFF 2304
#define KSOFF 4608
#define VSOFF 6912
#define GWOFF 13568
#define GBOFF 13824
#define WQ2U 6928
#define WK2U 7472
#define WV2U 8016
#define WO2U 8560
#define KA_SMEM (18208*4)
#define BKI(l,m) (9216 + (l)*68 + (m))

__global__ void __launch_bounds__(1024) kA(
    const float* __restrict__ chip0, const float* __restrict__ chip1,
    const float* __restrict__ chip2, const float* __restrict__ chip3,
    const float* __restrict__ bulk,
    const float* __restrict__ we_w, const float* __restrict__ we_b,
    const float* __restrict__ pos,
    const float* __restrict__ mn_g, const float* __restrict__ mn_b,
    const float* __restrict__ wq, const float* __restrict__ bq,
    const float* __restrict__ wk, const float* __restrict__ bk,
    const float* __restrict__ wv, const float* __restrict__ bv,
    const float* __restrict__ wo, const float* __restrict__ bo,
    const float* __restrict__ an_g, const float* __restrict__ an_b,
    const float* __restrict__ conv_w, const float* __restrict__ conv_b,
    const float* __restrict__ gate_w, const float* __restrict__ gate_b)
{
    extern __shared__ float sm[];
    u64* smu = reinterpret_cast<u64*>(sm);
    const int t = threadIdx.x;
    const int b = blockIdx.x >> 2, s = blockIdx.x & 3;
    const float* chip = (s==0)?chip0:(s==1)?chip1:(s==2)?chip2:chip3;

    for (int idx = t; idx < 512; idx += 1024) {
        const int r = idx >> 4, c2 = idx & 15;
        const int o = r*17 + c2;
        float2 a;
        a = *reinterpret_cast<const float2*>(&wq[idx*2]); smu[WQ2U + o] = *reinterpret_cast<u64*>(&a);
        a = *reinterpret_cast<const float2*>(&wk[idx*2]); smu[WK2U + o] = *reinterpret_cast<u64*>(&a);
        a = *reinterpret_cast<const float2*>(&wv[idx*2]); smu[WV2U + o] = *reinterpret_cast<u64*>(&a);
        a = *reinterpret_cast<const float2*>(&wo[idx*2]); smu[WO2U + o] = *reinterpret_cast<u64*>(&a);
    }
    for (int idx = t; idx < L_*L_; idx += 1024)
        sm[BKI(idx>>6, idx&63)] = bulk[b*L_*L_ + idx];
    if (t < 256) sm[GWOFF + t] = gate_w[t];
    if (t >= 256 && t < 288) sm[GBOFF + t - 256] = gate_b[t - 256];

    // phase 1
    {
        const int l = t >> 4, q = t & 15, c0 = q*2;
        const float sig = chip[b*L_ + l];
        const float2 ww = *reinterpret_cast<const float2*>(&we_w[c0]);
        const float2 wb = *reinterpret_cast<const float2*>(&we_b[c0]);
        const float2 pp = *reinterpret_cast<const float2*>(&pos[l*C_ + c0]);
        const float v0 = fmaf(sig, ww.x, wb.x) + pp.x;
        const float v1 = fmaf(sig, ww.y, wb.y) + pp.y;
        float s1 = v0 + v1, s2 = v0*v0 + v1*v1;
        #pragma unroll
        for (int o = 1; o < 16; o <<= 1) {
            s1 += __shfl_xor_sync(0xffffffffu, s1, o);
            s2 += __shfl_xor_sync(0xffffffffu, s2, o);
        }
        const float mean = s1*(1.f/C_);
        const float rstd = rsqrtf(s2*(1.f/C_) - mean*mean + 1e-5f);
        sm[xi(l,c0)]   = (v0-mean)*rstd*mn_g[c0]   + mn_b[c0];
        sm[xi(l,c0+1)] = (v1-mean)*rstd*mn_g[c0+1] + mn_b[c0+1];
    }
    __syncthreads();

    // phase 2
    {
        const int co = t & 31, lbase = (t >> 5) * 2;
        const int x0b = lbase*18,     k0h = keyf(lbase)   >> 1;
        const int x1b = (lbase+1)*18, k1h = keyf(lbase+1) >> 1;
        const int wrow = co*17;
        u64 aq0=0, aq1=0, ak0=0, ak1=0, av0=0, av1=0;
        #pragma unroll 8
        for (int c2 = 0; c2 < 16; c2++) {
            const u64 x0 = smu[x0b + (c2 ^ k0h)];
            const u64 x1 = smu[x1b + (c2 ^ k1h)];
            const u64 wqv = smu[WQ2U + wrow + c2];
            const u64 wkv = smu[WK2U + wrow + c2];
            const u64 wvv = smu[WV2U + wrow + c2];
            aq0 = fma2(x0, wqv, aq0); aq1 = fma2(x1, wqv, aq1);
            ak0 = fma2(x0, wkv, ak0); ak1 = fma2(x1, wkv, ak1);
            av0 = fma2(x0, wvv, av0); av1 = fma2(x1, wvv, av1);
        }
        const float ibq = bq[co], ibk = bk[co], ibv = bv[co];
        float2 f;
        f = unpack2(aq0); sm[QSOFF + xi(lbase,co)]   = f.x + f.y + ibq;
        f = unpack2(aq1); sm[QSOFF + xi(lbase+1,co)] = f.x + f.y + ibq;
        f = unpack2(ak0); sm[KSOFF + xi(lbase,co)]   = f.x + f.y + ibk;
        f = unpack2(ak1); sm[KSOFF + xi(lbase+1,co)] = f.x + f.y + ibk;
        f = unpack2(av0); sm[VSOFF + xi(lbase,co)]   = f.x + f.y + ibv;
        f = unpack2(av1); sm[VSOFF + xi(lbase+1,co)] = f.x + f.y + ibv;
    }
    __syncthreads();

    // phase 3: attention; gate split 4-ways, tanh sigmoid.
    {
        const int h = t >> 8, rem = t & 255;
        const int l = rem >> 2, quarter = rem & 3;
        const int hc = h*D_;
        const float rsd = 0.35355339059327373f;

        ulonglong2 qa = *reinterpret_cast<const ulonglong2*>(&sm[QSOFF + xi(l,hc)]);
        ulonglong2 qb = *reinterpret_cast<const ulonglong2*>(&sm[QSOFF + xi(l,hc+4)]);
        const u64 rsd2 = pack2(rsd, rsd);
        qa.x = mul2(qa.x, rsd2); qa.y = mul2(qa.y, rsd2);
        qb.x = mul2(qb.x, rsd2); qb.y = mul2(qb.y, rsd2);
        const float cw = conv_w[h], cb = conv_b[h];

        float Z = 0.f;
        u64 A0 = 0ull, A1 = 0ull, A2 = 0ull, A3 = 0ull;

        #pragma unroll 4
        for (int mm = 0; mm < 16; mm++) {
            const int m = mm*4 + quarter;
            const ulonglong2 ka = *reinterpret_cast<const ulonglong2*>(&sm[KSOFF + xi(m,hc)]);
            const ulonglong2 kb = *reinterpret_cast<const ulonglong2*>(&sm[KSOFF + xi(m,hc+4)]);
            u64 u = mul2(qa.x, ka.x);
            u = fma2(qa.y, ka.y, u);
            u = fma2(qb.x, kb.x, u);
            u = fma2(qb.y, kb.y, u);
            const float2 uf = unpack2(u);
            const float sc = uf.x + uf.y + fmaf(sm[BKI(l,m)], cw, cb);
            const float p = __expf(sc);
            Z += p;
            const u64 pp = pack2(p, p);
            const ulonglong2 va = *reinterpret_cast<const ulonglong2*>(&sm[VSOFF + xi(m,hc)]);
            const ulonglong2 vb = *reinterpret_cast<const ulonglong2*>(&sm[VSOFF + xi(m,hc+4)]);
            A0 = fma2(pp, va.x, A0); A1 = fma2(pp, va.y, A1);
            A2 = fma2(pp, vb.x, A2); A3 = fma2(pp, vb.y, A3);
        }
        #pragma unroll
        for (int o = 1; o < 4; o <<= 1) {
            Z  += __shfl_xor_sync(0xffffffffu, Z, o);
            A0 = add2(A0, __shfl_xor_sync(0xffffffffu, A0, o));
            A1 = add2(A1, __shfl_xor_sync(0xffffffffu, A1, o));
            A2 = add2(A2, __shfl_xor_sync(0xffffffffu, A2, o));
            A3 = add2(A3, __shfl_xor_sync(0xffffffffu, A3, o));
        }

        const float inv = 1.f/Z;
        const float2 f0 = unpack2(A0), f1 = unpack2(A1), f2 = unpack2(A2), f3 = unpack2(A3);
        float o[D_];
        o[0]=f0.x*inv; o[1]=f0.y*inv; o[2]=f1.x*inv; o[3]=f1.y*inv;
        o[4]=f2.x*inv; o[5]=f2.y*inv; o[6]=f3.x*inv; o[7]=f3.y*inv;
        const int d0 = quarter*2;
        float2 og;
        #pragma unroll
        for (int k = 0; k < 2; k++) {
            const int d = d0 + k;
            const float4 w0 = *reinterpret_cast<const float4*>(&sm[GWOFF + h*64 + d*8]);
            const float4 w1 = *reinterpret_cast<const float4*>(&sm[GWOFF + h*64 + d*8 + 4]);
            float g = sm[GBOFF + hc + d];
            g += w0.x*o[0] + w0.y*o[1] + w0.z*o[2] + w0.w*o[3];
            g += w1.x*o[4] + w1.y*o[5] + w1.z*o[6] + w1.w*o[7];
            (&og.x)[k] = o[d] * sigmoid_t(g);
        }
        __syncthreads();
        *reinterpret_cast<float2*>(&sm[QSOFF + xi(l, hc + d0)]) = og;
    }
    __syncthreads();

    // phase 4: wo + residual + LN(an) -> g_xbuf.
    {
        const int co = t & 31, lbase = (t >> 5) * 2;
        const int x0b = lbase*18,     k0h = keyf(lbase)   >> 1;
        const int x1b = (lbase+1)*18, k1h = keyf(lbase+1) >> 1;
        const int wrow = co*17;
        u64 a0 = 0, a1 = 0;
        #pragma unroll 8
        for (int c2 = 0; c2 < 16; c2++) {
            const u64 w = smu[WO2U + wrow + c2];
            a0 = fma2(smu[(QSOFF>>1) + x0b + (c2 ^ k0h)], w, a0);
            a1 = fma2(smu[(QSOFF>>1) + x1b + (c2 ^ k1h)], w, a1);
        }
        const float ib = bo[co];
        const float2 fa = unpack2(a0), fb = unpack2(a1);
        const float v0 = sm[xi(lbase,co)]   + fa.x + fa.y + ib;
        const float v1 = sm[xi(lbase+1,co)] + fb.x + fb.y + ib;

        u64 S1 = pack2(v0, v1), S2 = pack2(v0*v0, v1*v1);
        #pragma unroll
        for (int o = 1; o < 32; o <<= 1) {
            S1 = add2(S1, __shfl_xor_sync(0xffffffffu, S1, o));
            S2 = add2(S2, __shfl_xor_sync(0xffffffffu, S2, o));
        }
        const float2 s1 = unpack2(S1), s2 = unpack2(S2);
        const float m0 = s1.x*(1.f/C_), m1 = s1.y*(1.f/C_);
        const float r0 = rsqrtf(s2.x*(1.f/C_) - m0*m0 + 1e-5f);
        const float r1 = rsqrtf(s2.y*(1.f/C_) - m1*m1 + 1e-5f);
        const float ag = an_g[co], ab = an_b[co];
        float* dst = g_xbuf + ((b*S_ + s)*L_ + lbase)*C_ + co;
        dst[0]   = (v0 - m0)*r0*ag + ab;
        dst[C_]  = (v1 - m1)*r1*ag + ab;
    }
}

// ---------------------------------------------------------------------------
// Kernel kWB: grid = (b, i-group-of-16) = 128 blocks, 512 threads.
// Phase 5 retiled: warp = ii (single pass), lane owns j and j+32.
// MJ uses xi swizzle so rows j and j+32 are bank-disjoint.
// smem floats: MT@0 (2176), WIT@2176 (10240), RNV@12416 (64),
// MJ@12480 (2304, xi swz), PRM@14784 (49). Total 14840 fl = 59360 B.
// ---------------------------------------------------------------------------
#define MT   0
#define WIT  2176
#define RNV  12416
#define MJ   12480
#define PRM  14784
#define KWB_SMEM (14840*4)

__global__ void __launch_bounds__(512) kWB(
    const float* __restrict__ pp_w, const float* __restrict__ pp_b,
    const float* __restrict__ ada_g, const float* __restrict__ ada_b,
    const float* __restrict__ ada_alpha, float* __restrict__ out)
{
    extern __shared__ float smw[];
    const int t = threadIdx.x;
    const int b = blockIdx.x >> 2, i0 = (blockIdx.x & 3) * 16;
    const float* xb = g_xbuf + b*S_*L_*C_;

    if (t < CP_)         smw[PRM + t]  = pp_b[t];
    else if (t < 2*CP_)  smw[PRM + t]  = ada_g[t - CP_];
    else if (t < 3*CP_)  smw[PRM + t]  = ada_b[t - 2*CP_];
    else if (t == 3*CP_) smw[PRM + 48] = ada_alpha[0];

    // phase 1: max over tracks -> mT[c][j]
    for (int idx = t; idx < L_*C_; idx += 512) {
        const int j = idx >> 5, c = idx & 31;
        const float m = fmaxf(fmaxf(xb[idx], xb[2048+idx]),
                              fmaxf(xb[4096+idx], xb[6144+idx]));
        smw[MT + c*68 + j] = m;
    }
    __syncthreads();

    // phase 2: rinv per j
    if (t < L_) {
        float ss = 0.f;
        #pragma unroll
        for (int c = 0; c < C_; c++) { const float v = smw[MT + c*68 + t]; ss += v*v; }
        smw[RNV + t] = rsqrtf(ss);
    }
    __syncthreads();

    // phase 3: normalize mT; write transposed MJ[j][c] (xi swizzle)
    for (int idx = t; idx < L_*C_; idx += 512) {
        const int j = idx & 63, c = idx >> 6;
        const float v = smw[MT + c*68 + j] * smw[RNV + j];
        smw[MT + c*68 + j] = v;
        smw[MJ + xi(j, c)] = v;
    }
    __syncthreads();

    // phase 4: wi. warp = p, lane = d; pp_w column in regs; WIT p-XOR key.
    {
        const int p = t >> 5, d = t & 31;
        const int pk = p ^ (((d >> 3) & 3) << 2);
        float wreg[32];
        #pragma unroll
        for (int c = 0; c < 32; c++) wreg[c] = pp_w[p*1024 + c*32 + d];
        u64 acc[8];
        #pragma unroll
        for (int k = 0; k < 8; k++) acc[k] = 0ull;
        #pragma unroll 4
        for (int c = 0; c < 32; c++) {
            const float* mb = &smw[MT + c*68 + i0];
            const ulonglong2 ma = *reinterpret_cast<const ulonglong2*>(mb);
            const ulonglong2 mbv = *reinterpret_cast<const ulonglong2*>(mb+4);
            const ulonglong2 mc = *reinterpret_cast<const ulonglong2*>(mb+8);
            const ulonglong2 md = *reinterpret_cast<const ulonglong2*>(mb+12);
            const u64 w2 = pack2(wreg[c], wreg[c]);
            acc[0] = fma2(ma.x,  w2, acc[0]); acc[1] = fma2(ma.y,  w2, acc[1]);
            acc[2] = fma2(mbv.x, w2, acc[2]); acc[3] = fma2(mbv.y, w2, acc[3]);
            acc[4] = fma2(mc.x,  w2, acc[4]); acc[5] = fma2(mc.y,  w2, acc[5]);
            acc[6] = fma2(md.x,  w2, acc[6]); acc[7] = fma2(md.y,  w2, acc[7]);
        }
        #pragma unroll
        for (int k = 0; k < 8; k++) {
            const float2 f = unpack2(acc[k]);
            smw[WIT + (2*k)*640   + d*20 + pk] = f.x;
            smw[WIT + (2*k+1)*640 + d*20 + pk] = f.y;
        }
    }
    __syncthreads();

    // phase 5: warp = ii; lane handles j = lane and lane+32; all 16 p local.
    {
        const int ii = t >> 5, lane = t & 31;
        const int i = i0 + ii;
        const float alpha = smw[PRM + 48];

        u64 acc0[8], acc1[8];
        #pragma unroll
        for (int k = 0; k < 8; k++) { acc0[k] = 0ull; acc1[k] = 0ull; }

        #pragma unroll
        for (int cg = 0; cg < 8; cg++) {
            const float4 mja = *reinterpret_cast<const float4*>(&smw[MJ + xi(lane,    cg*4)]);
            const float4 mjb = *reinterpret_cast<const float4*>(&smw[MJ + xi(lane+32, cg*4)]);
            #pragma unroll
            for (int cc = 0; cc < 4; cc++) {
                const int c = cg*4 + cc;
                const int kk = (c >> 3) & 3;
                const float ma = (&mja.x)[cc], mb = (&mjb.x)[cc];
                const u64 m2a = pack2(ma, ma);
                const u64 m2b = pack2(mb, mb);
                const float* wb = &smw[WIT + ii*640 + c*20];
                ulonglong2 wv[4];
                wv[0] = *reinterpret_cast<const ulonglong2*>(wb);       // broadcast
                wv[1] = *reinterpret_cast<const ulonglong2*>(wb+4);
                wv[2] = *reinterpret_cast<const ulonglong2*>(wb+8);
                wv[3] = *reinterpret_cast<const ulonglong2*>(wb+12);
                #pragma unroll
                for (int u = 0; u < 4; u++) {
                    const int g = u ^ kk;
                    acc0[2*g]   = fma2(wv[u].x, m2a, acc0[2*g]);
                    acc0[2*g+1] = fma2(wv[u].y, m2a, acc0[2*g+1]);
                    acc1[2*g]   = fma2(wv[u].x, m2b, acc1[2*g]);
                    acc1[2*g+1] = fma2(wv[u].y, m2b, acc1[2*g+1]);
                }
            }
        }

        #pragma unroll
        for (int half = 0; half < 2; half++) {
            const int jj = lane + half*32;
            u64* acc = half ? acc1 : acc0;
            float feat[16];
            float s1 = 0.f, s2 = 0.f;
            #pragma unroll
            for (int k = 0; k < 8; k++) {
                const float2 f = unpack2(acc[k]);
                const float v0 = f.x + smw[PRM + 2*k];
                const float v1 = f.y + smw[PRM + 2*k+1];
                feat[2*k] = v0; feat[2*k+1] = v1;
                s1 += v0 + v1; s2 += v0*v0 + v1*v1;
            }
            const float mu = s1*(1.f/CP_);
            const float rstd = rsqrtf(s2*(1.f/CP_) - mu*mu + 1e-5f);

            #pragma unroll
            for (int p = 0; p < CP_; p++) {
                const float v = feat[p];
                const float ln = (v - mu)*rstd*smw[PRM + 16 + p] + smw[PRM + 32 + p];
                const float val = v + alpha*ln;
                out[((b*CP_ + p)*L_ + i)*L_ + jj] = val * sigmoid_t(val);
            }
        }
    }
}

extern "C" void kernel_launch(void* const* d_in, const int* in_sizes, int n_in,
                              void* d_out, int out_size) {
    const float* in[29];
    for (int i = 0; i < 29 && i < n_in; i++) in[i] = (const float*)d_in[i];

    cudaFuncSetAttribute(kA,  cudaFuncAttributeMaxDynamicSharedMemorySize, KA_SMEM);
    cudaFuncSetAttribute(kWB, cudaFuncAttributeMaxDynamicSharedMemorySize, KWB_SMEM);

    kA<<<B_*S_, 1024, KA_SMEM>>>(in[0], in[1], in[2], in[3], in[4],
                                 in[5], in[6], in[7], in[8], in[9],
                                 in[10], in[11], in[12], in[13], in[14], in[15],
                                 in[16], in[17], in[18], in[19],
                                 in[20], in[21], in[22], in[23]);
    kWB<<<B_*4, 512, KWB_SMEM>>>(in[24], in[25], in[26], in[27], in[28],
                                 (float*)d_out);
}